// round 11
// baseline (speedup 1.0000x reference)
#include <cuda_runtime.h>
#include <cuda_bf16.h>
#include <mma.h>

using namespace nvcuda;

#define SQ   1024
#define DH   64
#define NBH  32
#define TS   72   // bf16 tile row stride (conflict-free ldmatrix)

__device__ float g_partial[16 * NBH * SQ];
__device__ float g_rinv[NBH * SQ];
__device__ __align__(16) __nv_bfloat16 g_vh[NBH * SQ * DH];  // V hi [bh][k][d]
__device__ __align__(16) __nv_bfloat16 g_vl[NBH * SQ * DH];  // V lo

// Split fp32x4 -> packed bf16 hi/lo (2x bf16x2 each)
static __device__ __forceinline__ void cvt_pair(float4 v, uint2& h, uint2& l) {
    __nv_bfloat16 hx = __float2bfloat16(v.x);
    __nv_bfloat16 hy = __float2bfloat16(v.y);
    __nv_bfloat16 hz = __float2bfloat16(v.z);
    __nv_bfloat16 hw = __float2bfloat16(v.w);
    h.x = ((unsigned)__bfloat16_as_ushort(hy) << 16) | __bfloat16_as_ushort(hx);
    h.y = ((unsigned)__bfloat16_as_ushort(hw) << 16) | __bfloat16_as_ushort(hz);
    unsigned short gx = __bfloat16_as_ushort(__float2bfloat16(v.x - __bfloat162float(hx)));
    unsigned short gy = __bfloat16_as_ushort(__float2bfloat16(v.y - __bfloat162float(hy)));
    unsigned short gz = __bfloat16_as_ushort(__float2bfloat16(v.z - __bfloat162float(hz)));
    unsigned short gw = __bfloat16_as_ushort(__float2bfloat16(v.w - __bfloat162float(hw)));
    l.x = ((unsigned)gy << 16) | gx;
    l.y = ((unsigned)gw << 16) | gz;
}

// ---------------------------------------------------------------------------
__global__ __launch_bounds__(256) void k_vsplit(const float* __restrict__ V)
{
    const int i = (blockIdx.x * 256 + threadIdx.x) * 4;
    float4 v = *(const float4*)(V + i);
    uint2 h, l;
    cvt_pair(v, h, l);
    *(uint2*)((char*)g_vh + i * 2) = h;
    *(uint2*)((char*)g_vl + i * 2) = l;
}

// ---------------------------------------------------------------------------
// Kernel 1: E = exp(QK^T/8 + ia_type + ia_feat), mask->0.
// Tile 128q x 64k, 256 threads, smem 55296 B -> 4 blocks/SM.
// Warps: 4 row-groups x 2 col-groups, warp tile 32x32.
// ---------------------------------------------------------------------------
__global__ __launch_bounds__(256) void k_scores(
    const float* __restrict__ Q, const float* __restrict__ K,
    const float* __restrict__ iat, const float* __restrict__ iaf,
    const unsigned* __restrict__ mask, float* __restrict__ E)
{
    const int kb = blockIdx.x, qb = blockIdx.y, bh = blockIdx.z;
    extern __shared__ char sm[];
    __nv_bfloat16* Qh = (__nv_bfloat16*)sm;          // 128 x 72
    __nv_bfloat16* Ql = Qh + 128 * TS;
    __nv_bfloat16* Kh = Ql + 128 * TS;               // 64 x 72
    __nv_bfloat16* Kl = Kh + 64 * TS;
    float* Ss = (float*)sm;                          // 128 x 68 f32 (reuse)

    const int tid = threadIdx.x;
    const int wid = tid >> 5;
    const int hw = tid >> 4, ln16 = tid & 15;

    // Convert Q (2 thr/row) and K (4 thr/row) to bf16 hi/lo
    {
        const int rowq = tid >> 1, halfq = tid & 1;
        const float* qr = Q + ((size_t)bh * SQ + qb * 128 + rowq) * DH + halfq * 32;
#pragma unroll
        for (int i = 0; i < 8; i++) {
            const int o = rowq * TS + halfq * 32 + i * 4;
            uint2 h, l;
            float4 v = *(const float4*)(qr + i * 4);
            cvt_pair(v, h, l);
            *(uint2*)(Qh + o) = h;
            *(uint2*)(Ql + o) = l;
        }
        const int rowk = tid >> 2, qk = tid & 3;
        const float* kr = K + ((size_t)bh * SQ + kb * 64 + rowk) * DH + qk * 16;
#pragma unroll
        for (int i = 0; i < 4; i++) {
            const int o = rowk * TS + qk * 16 + i * 4;
            uint2 h, l;
            float4 v = *(const float4*)(kr + i * 4);
            cvt_pair(v, h, l);
            *(uint2*)(Kh + o) = h;
            *(uint2*)(Kl + o) = l;
        }
    }
    __syncthreads();

    const int r0 = (wid >> 1) * 32;   // warp rows
    const int c0 = (wid & 1) * 32;    // warp cols

    wmma::fragment<wmma::accumulator, 16, 16, 16, float> acc[2][2];
#pragma unroll
    for (int i = 0; i < 2; i++)
#pragma unroll
        for (int j = 0; j < 2; j++) wmma::fill_fragment(acc[i][j], 0.f);

#pragma unroll
    for (int d0 = 0; d0 < DH; d0 += 16) {
        wmma::fragment<wmma::matrix_a, 16, 16, 16, __nv_bfloat16, wmma::row_major> ah[2], al[2];
        wmma::fragment<wmma::matrix_b, 16, 16, 16, __nv_bfloat16, wmma::col_major> bh[2], bl[2];
#pragma unroll
        for (int i = 0; i < 2; i++) {
            wmma::load_matrix_sync(ah[i], Qh + (r0 + i * 16) * TS + d0, TS);
            wmma::load_matrix_sync(al[i], Ql + (r0 + i * 16) * TS + d0, TS);
        }
#pragma unroll
        for (int j = 0; j < 2; j++) {
            wmma::load_matrix_sync(bh[j], Kh + (c0 + j * 16) * TS + d0, TS);
            wmma::load_matrix_sync(bl[j], Kl + (c0 + j * 16) * TS + d0, TS);
        }
#pragma unroll
        for (int i = 0; i < 2; i++)
#pragma unroll
            for (int j = 0; j < 2; j++) {
                wmma::mma_sync(acc[i][j], ah[i], bh[j], acc[i][j]);
                wmma::mma_sync(acc[i][j], ah[i], bl[j], acc[i][j]);
                wmma::mma_sync(acc[i][j], al[i], bh[j], acc[i][j]);
            }
    }
    __syncthreads();   // tiles dead

#pragma unroll
    for (int i = 0; i < 2; i++)
#pragma unroll
        for (int j = 0; j < 2; j++)
            wmma::store_matrix_sync(Ss + (r0 + i * 16) * 68 + c0 + j * 16,
                                    acc[i][j], 68, wmma::mem_row_major);
    __syncthreads();

    // Coalesced epilogue: half-warp per 64-wide row, 8 iterations
    const size_t base = (((size_t)bh * SQ) + qb * 128) * SQ + (size_t)kb * 64;
#pragma unroll 4
    for (int it = 0; it < 8; it++) {
        const int row = it * 16 + hw;
        const int c   = ln16 << 2;
        const size_t g = base + (size_t)row * SQ + c;
        float4 a  = *(const float4*)(iat + g);
        float4 b  = *(const float4*)(iaf + g);
        uint4  m  = *(const uint4*)(mask + g);
        float4 sv = *(const float4*)(Ss + row * 68 + c);
        float4 e;
        e.x = m.x ? 0.f : __expf(fmaf(sv.x, 0.125f, a.x + b.x));
        e.y = m.y ? 0.f : __expf(fmaf(sv.y, 0.125f, a.y + b.y));
        e.z = m.z ? 0.f : __expf(fmaf(sv.z, 0.125f, a.z + b.z));
        e.w = m.w ? 0.f : __expf(fmaf(sv.w, 0.125f, a.w + b.w));
        *(float4*)(E + g) = e;

        float part = (e.x + e.y) + (e.z + e.w);
#pragma unroll
        for (int o = 8; o > 0; o >>= 1)
            part += __shfl_xor_sync(0xffffffffu, part, o);
        if (ln16 == 0)
            g_partial[(size_t)kb * (NBH * SQ) + (size_t)bh * SQ
                      + qb * 128 + row] = part;
    }
}

// ---------------------------------------------------------------------------
__global__ __launch_bounds__(256) void k_rowsum()
{
    const int r = blockIdx.x * 256 + threadIdx.x;
    float s = 0.f;
#pragma unroll
    for (int kb = 0; kb < 16; kb++) s += g_partial[kb * (NBH * SQ) + r];
    g_rinv[r] = 1.f / s;
}

// ---------------------------------------------------------------------------
// Kernel 2: normalize attn in place + ctx = rinv * (E @ V).
// Tile 64q x 64d; 16 k-tiles of 64; 256 threads; register-prefetch pipeline.
// Warps: 4 row-groups (16 rows) x 2 col-groups (32 cols).
// ---------------------------------------------------------------------------
__global__ __launch_bounds__(256) void k_pv(
    float* __restrict__ attn, float* __restrict__ ctx)
{
    const int qb = blockIdx.x, bh = blockIdx.y;  // qb 0..15
    extern __shared__ char sm[];
    float* sRi = (float*)sm;                                 // 64 f32 (256 B)
    __nv_bfloat16* Eh = (__nv_bfloat16*)(sm + 256);          // 64 x 72
    __nv_bfloat16* El = Eh + 64 * TS;
    __nv_bfloat16* Vh = El + 64 * TS;                        // 64 x 72
    __nv_bfloat16* Vl = Vh + 64 * TS;
    float* Ss = (float*)(sm + 256);                          // 64 x 72 f32 (reuse)

    const int tid = threadIdx.x;
    const int wid = tid >> 5;
    const int rowe = tid >> 2, qc = (tid & 3) * 16;   // thread's row / col base

    if (tid < 64)
        sRi[tid] = g_rinv[(size_t)bh * SQ + qb * 64 + tid];
    __syncthreads();
    const float rvq = sRi[rowe];

    wmma::fragment<wmma::accumulator, 16, 16, 16, float> acc[2];
    wmma::fill_fragment(acc[0], 0.f);
    wmma::fill_fragment(acc[1], 0.f);

    const size_t abase = ((size_t)bh * SQ + qb * 64) * SQ;
    const __nv_bfloat16* vhb = g_vh + (size_t)bh * SQ * DH;
    const __nv_bfloat16* vlb = g_vl + (size_t)bh * SQ * DH;

    // Prefetch t=0
    float4 ev[4];
    uint4 pvh[2], pvl[2];
    {
        const float* ap = attn + abase + (size_t)rowe * SQ + qc;
#pragma unroll
        for (int i = 0; i < 4; i++) ev[i] = *(const float4*)(ap + i * 4);
        const size_t go = (size_t)rowe * DH + qc;
        pvh[0] = *(const uint4*)(vhb + go);
        pvh[1] = *(const uint4*)(vhb + go + 8);
        pvl[0] = *(const uint4*)(vlb + go);
        pvl[1] = *(const uint4*)(vlb + go + 8);
    }

    const int rg = wid >> 1, cg = wid & 1;

    for (int t = 0; t < 16; t++) {
        const int k0 = t * 64;
        // Store phase: normalize-WB attn, cvt E -> smem, V -> smem
        {
            float* ap = attn + abase + (size_t)rowe * SQ + k0 + qc;
#pragma unroll
            for (int i = 0; i < 4; i++) {
                uint2 h, l;
                cvt_pair(ev[i], h, l);
                const int o = rowe * TS + qc + i * 4;
                *(uint2*)(Eh + o) = h;
                *(uint2*)(El + o) = l;
                float4 v = ev[i];
                v.x *= rvq; v.y *= rvq; v.z *= rvq; v.w *= rvq;
                *(float4*)(ap + i * 4) = v;
            }
            const int o = rowe * TS + qc;
            *(uint4*)(Vh + o)     = pvh[0];
            *(uint4*)(Vh + o + 8) = pvh[1];
            *(uint4*)(Vl + o)     = pvl[0];
            *(uint4*)(Vl + o + 8) = pvl[1];
        }
        __syncthreads();

        // Prefetch t+1 (loads overlap with MMA below)
        if (t < 15) {
            const int k1 = k0 + 64;
            const float* ap = attn + abase + (size_t)rowe * SQ + k1 + qc;
#pragma unroll
            for (int i = 0; i < 4; i++) ev[i] = *(const float4*)(ap + i * 4);
            const size_t go = (size_t)(k1 + rowe) * DH + qc;
            pvh[0] = *(const uint4*)(vhb + go);
            pvh[1] = *(const uint4*)(vhb + go + 8);
            pvl[0] = *(const uint4*)(vlb + go);
            pvl[1] = *(const uint4*)(vlb + go + 8);
        }

        // MMA phase
#pragma unroll
        for (int kk = 0; kk < 4; kk++) {
            wmma::fragment<wmma::matrix_a, 16, 16, 16, __nv_bfloat16, wmma::row_major> ah, al;
            wmma::fragment<wmma::matrix_b, 16, 16, 16, __nv_bfloat16, wmma::row_major> bhf[2], blf[2];
            wmma::load_matrix_sync(ah, Eh + (rg * 16) * TS + kk * 16, TS);
            wmma::load_matrix_sync(al, El + (rg * 16) * TS + kk * 16, TS);
#pragma unroll
            for (int j = 0; j < 2; j++) {
                wmma::load_matrix_sync(bhf[j], Vh + (kk * 16) * TS + cg * 32 + j * 16, TS);
                wmma::load_matrix_sync(blf[j], Vl + (kk * 16) * TS + cg * 32 + j * 16, TS);
            }
#pragma unroll
            for (int j = 0; j < 2; j++) {
                wmma::mma_sync(acc[j], ah, bhf[j], acc[j]);
                wmma::mma_sync(acc[j], ah, blf[j], acc[j]);
                wmma::mma_sync(acc[j], al, bhf[j], acc[j]);
            }
        }
        __syncthreads();
    }

    // Stage accumulators (tiles dead), stride 72 f32
#pragma unroll
    for (int j = 0; j < 2; j++)
        wmma::store_matrix_sync(Ss + (rg * 16) * TS + cg * 32 + j * 16,
                                acc[j], TS, wmma::mem_row_major);
    __syncthreads();

    // Coalesced ctx writes
    {
        float* cp = ctx + ((size_t)bh * SQ + qb * 64 + rowe) * DH + qc;
#pragma unroll
        for (int i = 0; i < 4; i++) {
            float4 o = *(const float4*)(Ss + rowe * TS + qc + i * 4);
            o.x *= rvq; o.y *= rvq; o.z *= rvq; o.w *= rvq;
            *(float4*)(cp + i * 4) = o;
        }
    }
}

// ---------------------------------------------------------------------------
extern "C" void kernel_launch(void* const* d_in, const int* in_sizes, int n_in,
                              void* d_out, int out_size)
{
    const float*    Q    = (const float*)d_in[0];
    const float*    K    = (const float*)d_in[1];
    const float*    V    = (const float*)d_in[2];
    const unsigned* mask = (const unsigned*)d_in[4];  // attn_mask_if
    const float*    iat  = (const float*)d_in[5];
    const float*    iaf  = (const float*)d_in[6];

    float* ctx  = (float*)d_out;
    float* attn = ctx + (size_t)NBH * SQ * DH;

    const int smem1 = (2 * 128 * TS + 2 * 64 * TS) * 2;   // 55296
    const int smem2 = 256 + 4 * 64 * TS * 2;              // 37120
    cudaFuncSetAttribute(k_scores, cudaFuncAttributeMaxDynamicSharedMemorySize, smem1);
    cudaFuncSetAttribute(k_pv,     cudaFuncAttributeMaxDynamicSharedMemorySize, smem2);

    k_vsplit<<<(NBH * SQ * DH) / 1024, 256>>>(V);

    dim3 g1(16, 8, NBH);
    k_scores<<<g1, 256, smem1>>>(Q, K, iat, iaf, mask, attn);

    k_rowsum<<<(NBH * SQ) / 256, 256>>>();

    dim3 g2(16, NBH);
    k_pv<<<g2, 256, smem2>>>(attn, ctx);
}

// round 17
// speedup vs baseline: 1.4066x; 1.4066x over previous
#include <cuda_runtime.h>
#include <cuda_bf16.h>
#include <mma.h>

using namespace nvcuda;

#define SQ   1024
#define DH   64
#define NBH  32
#define TS   72   // bf16 tile row stride (conflict-free ldmatrix)
#define KSPLIT 4

__device__ float g_partial[8 * NBH * SQ];
__device__ float g_rinv[NBH * SQ];
__device__ __align__(16) __nv_bfloat16 g_vh[NBH * SQ * DH];
__device__ __align__(16) __nv_bfloat16 g_vl[NBH * SQ * DH];
__device__ __align__(16) float g_pctx[KSPLIT][NBH * SQ * DH];

static __device__ __forceinline__ void cvt_pair(float4 v, uint2& h, uint2& l) {
    __nv_bfloat16 hx = __float2bfloat16(v.x);
    __nv_bfloat16 hy = __float2bfloat16(v.y);
    __nv_bfloat16 hz = __float2bfloat16(v.z);
    __nv_bfloat16 hw = __float2bfloat16(v.w);
    h.x = ((unsigned)__bfloat16_as_ushort(hy) << 16) | __bfloat16_as_ushort(hx);
    h.y = ((unsigned)__bfloat16_as_ushort(hw) << 16) | __bfloat16_as_ushort(hz);
    unsigned short gx = __bfloat16_as_ushort(__float2bfloat16(v.x - __bfloat162float(hx)));
    unsigned short gy = __bfloat16_as_ushort(__float2bfloat16(v.y - __bfloat162float(hy)));
    unsigned short gz = __bfloat16_as_ushort(__float2bfloat16(v.z - __bfloat162float(hz)));
    unsigned short gw = __bfloat16_as_ushort(__float2bfloat16(v.w - __bfloat162float(hw)));
    l.x = ((unsigned)gy << 16) | gx;
    l.y = ((unsigned)gw << 16) | gz;
}

// ---------------------------------------------------------------------------
__global__ __launch_bounds__(256) void k_vsplit(const float* __restrict__ V)
{
    const int i = (blockIdx.x * 256 + threadIdx.x) * 4;
    float4 v = *(const float4*)(V + i);
    uint2 h, l;
    cvt_pair(v, h, l);
    *(uint2*)((char*)g_vh + i * 2) = h;
    *(uint2*)((char*)g_vl + i * 2) = l;
}

// ---------------------------------------------------------------------------
// Kernel 1 (R3 SIMT fp32, proven 147us): E = exp(QK^T/8 + biases), mask->0.
// 128q x 128k tile, 256 threads, 8x8 register GEMM, smem-staged epilogue.
// ---------------------------------------------------------------------------
__global__ __launch_bounds__(256) void k_scores(
    const float* __restrict__ Q, const float* __restrict__ K,
    const float* __restrict__ iat, const float* __restrict__ iaf,
    const unsigned int* __restrict__ mask, float* __restrict__ E)
{
    const int kb = blockIdx.x;
    const int qb = blockIdx.y;
    const int bh = blockIdx.z;

    extern __shared__ char smx[];
    float* sm = (float*)smx;
    float* Qs = sm;                    // 128 x 68
    float* Ks = sm + 128 * 68;         // 128 x 68

    const int tid = threadIdx.x;
    const int tx = tid & 15;
    const int ty = tid >> 4;
    const int lane = tid & 31;
    const int w = tid >> 5;

    const float* Qg = Q + ((size_t)bh * SQ + (size_t)qb * 128) * DH;
    const float* Kg = K + ((size_t)bh * SQ + (size_t)kb * 128) * DH;

#pragma unroll
    for (int it = 0; it < 8; it++) {
        int f4  = tid + it * 256;
        int row = f4 >> 4;
        int c4  = (f4 & 15) << 2;
        *(float4*)(Qs + row * 68 + c4) = *(const float4*)(Qg + row * DH + c4);
        *(float4*)(Ks + row * 68 + c4) = *(const float4*)(Kg + row * DH + c4);
    }
    __syncthreads();

    float acc[8][8];
#pragma unroll
    for (int i = 0; i < 8; i++)
#pragma unroll
        for (int j = 0; j < 8; j++) acc[i][j] = 0.f;

#pragma unroll 4
    for (int d = 0; d < DH; d++) {
        float qv[8], kv[8];
#pragma unroll
        for (int i = 0; i < 8; i++) qv[i] = Qs[(ty + i * 16) * 68 + d];
#pragma unroll
        for (int j = 0; j < 8; j++) kv[j] = Ks[(tx + j * 16) * 68 + d];
#pragma unroll
        for (int i = 0; i < 8; i++)
#pragma unroll
            for (int j = 0; j < 8; j++)
                acc[i][j] = fmaf(qv[i], kv[j], acc[i][j]);
    }
    __syncthreads();

    // Stage accumulators through smem (stride 132: float4-aligned rows)
    float* Ss = sm;                    // 128 x 132 = 67584 B (fits in 69632)
#pragma unroll
    for (int i = 0; i < 8; i++)
#pragma unroll
        for (int j = 0; j < 8; j++)
            Ss[(ty + i * 16) * 132 + tx + j * 16] = acc[i][j];
    __syncthreads();

    // Coalesced epilogue: one warp = one full row per iteration
    const size_t base = (((size_t)bh * SQ) + (size_t)qb * 128) * SQ
                      + (size_t)kb * 128;
#pragma unroll 4
    for (int it = 0; it < 16; it++) {
        const int row = it * 8 + w;
        const int c   = lane << 2;
        const size_t g = base + (size_t)row * SQ + c;
        float4 a = *(const float4*)(iat + g);
        float4 b = *(const float4*)(iaf + g);
        uint4  m = *(const uint4*)(mask + g);
        float4 sv = *(const float4*)(Ss + row * 132 + c);
        float4 e;
        e.x = m.x ? 0.f : __expf(fmaf(sv.x, 0.125f, a.x + b.x));
        e.y = m.y ? 0.f : __expf(fmaf(sv.y, 0.125f, a.y + b.y));
        e.z = m.z ? 0.f : __expf(fmaf(sv.z, 0.125f, a.z + b.z));
        e.w = m.w ? 0.f : __expf(fmaf(sv.w, 0.125f, a.w + b.w));
        *(float4*)(E + g) = e;

        float part = (e.x + e.y) + (e.z + e.w);
#pragma unroll
        for (int o = 16; o > 0; o >>= 1)
            part += __shfl_xor_sync(0xffffffffu, part, o);
        if (lane == 0)
            g_partial[(size_t)kb * (NBH * SQ) + (size_t)bh * SQ
                      + (size_t)qb * 128 + row] = part;
    }
}

// ---------------------------------------------------------------------------
__global__ __launch_bounds__(256) void k_rowsum()
{
    const int r = blockIdx.x * 256 + threadIdx.x;
    float s = 0.f;
#pragma unroll
    for (int kb = 0; kb < 8; kb++) s += g_partial[kb * (NBH * SQ) + r];
    g_rinv[r] = 1.f / s;
}

// ---------------------------------------------------------------------------
// Kernel 2 (R10 k-split WMMA, proven 114us): normalize attn in place +
// partial ctx = E @ V over a k-range.
// Grid: 8 qb x 32 bh x 4 ks; block 128q x 64d over 4 k-tiles of 64.
// ---------------------------------------------------------------------------
__global__ __launch_bounds__(256) void k_pv(
    float* __restrict__ attn)
{
    const int qb = blockIdx.x, bh = blockIdx.y, ks = blockIdx.z;
    extern __shared__ char smx[];
    float* sRi = (float*)smx;                                // 128 f32
    __nv_bfloat16* Eh = (__nv_bfloat16*)(smx + 512);         // 128 x 72
    __nv_bfloat16* El = Eh + 128 * TS;
    __nv_bfloat16* Vh = El + 128 * TS;                       // 64 x 72
    __nv_bfloat16* Vl = Vh + 64 * TS;
    float* Ss = (float*)(smx + 512);                         // 128 x 72 f32 (reuse)

    const int tid = threadIdx.x;
    const int wid = tid >> 5;
    const int hw = tid >> 4, ln16 = tid & 15;

    if (tid < 128)
        sRi[tid] = g_rinv[(size_t)bh * SQ + qb * 128 + tid];
    __syncthreads();

    wmma::fragment<wmma::accumulator, 16, 16, 16, float> acc[4];
#pragma unroll
    for (int j = 0; j < 4; j++) wmma::fill_fragment(acc[j], 0.f);

    const size_t abase = ((size_t)bh * SQ + qb * 128) * SQ;
    const __nv_bfloat16* vhb = g_vh + (size_t)bh * SQ * DH;
    const __nv_bfloat16* vlb = g_vl + (size_t)bh * SQ * DH;

    for (int t = 0; t < 4; t++) {
        const int k0 = (ks * 4 + t) * 64;
        // E tile 128x64: half-warp per row; bf16 split + fused normalize WB
#pragma unroll
        for (int it = 0; it < 8; it++) {
            const int row = it * 16 + hw;
            float* ap = attn + abase + (size_t)row * SQ + k0 + ln16 * 4;
            float4 v = *(const float4*)ap;
            uint2 h, l;
            cvt_pair(v, h, l);
            const int o = row * TS + ln16 * 4;
            *(uint2*)(Eh + o) = h;
            *(uint2*)(El + o) = l;
            const float rv = sRi[row];
            v.x *= rv; v.y *= rv; v.z *= rv; v.w *= rv;
            *(float4*)ap = v;
        }
        // V tiles 64x64 bf16 hi/lo
#pragma unroll
        for (int i = 0; i < 2; i++) {
            const int idx = tid + i * 256;
            const int r = idx >> 3, c8 = (idx & 7) * 8;
            const size_t go = (size_t)(k0 + r) * DH + c8;
            *(uint4*)(Vh + r * TS + c8) = *(const uint4*)(vhb + go);
            *(uint4*)(Vl + r * TS + c8) = *(const uint4*)(vlb + go);
        }
        __syncthreads();

#pragma unroll
        for (int kk = 0; kk < 4; kk++) {
            wmma::fragment<wmma::matrix_a, 16, 16, 16, __nv_bfloat16, wmma::row_major> ah, al;
            wmma::fragment<wmma::matrix_b, 16, 16, 16, __nv_bfloat16, wmma::row_major> bhf[4], blf[4];
            wmma::load_matrix_sync(ah, Eh + (wid * 16) * TS + kk * 16, TS);
            wmma::load_matrix_sync(al, El + (wid * 16) * TS + kk * 16, TS);
#pragma unroll
            for (int j = 0; j < 4; j++) {
                wmma::load_matrix_sync(bhf[j], Vh + (kk * 16) * TS + j * 16, TS);
                wmma::load_matrix_sync(blf[j], Vl + (kk * 16) * TS + j * 16, TS);
            }
#pragma unroll
            for (int j = 0; j < 4; j++) {
                wmma::mma_sync(acc[j], ah, bhf[j], acc[j]);
                wmma::mma_sync(acc[j], ah, blf[j], acc[j]);
                wmma::mma_sync(acc[j], al, bhf[j], acc[j]);
            }
        }
        __syncthreads();
    }

    // Stage accumulators (tiles dead), stride 72 f32
#pragma unroll
    for (int j = 0; j < 4; j++)
        wmma::store_matrix_sync(Ss + (wid * 16) * TS + j * 16, acc[j], TS,
                                wmma::mem_row_major);
    __syncthreads();

    float* pc = g_pctx[ks] + ((size_t)bh * SQ + qb * 128) * DH;
#pragma unroll
    for (int it = 0; it < 8; it++) {
        const int row = it * 16 + hw;
        float4 o = *(const float4*)(Ss + row * TS + ln16 * 4);
        *(float4*)(pc + (size_t)row * DH + ln16 * 4) = o;
    }
}

// ---------------------------------------------------------------------------
__global__ __launch_bounds__(256) void k_ctx(float* __restrict__ ctx)
{
    const size_t f = (size_t)blockIdx.x * 256 + threadIdx.x;
    const size_t i = f * 4;
    float4 s = *(const float4*)(g_pctx[0] + i);
    float4 a = *(const float4*)(g_pctx[1] + i);
    float4 b = *(const float4*)(g_pctx[2] + i);
    float4 c = *(const float4*)(g_pctx[3] + i);
    s.x = (s.x + a.x) + (b.x + c.x);
    s.y = (s.y + a.y) + (b.y + c.y);
    s.z = (s.z + a.z) + (b.z + c.z);
    s.w = (s.w + a.w) + (b.w + c.w);
    const float rv = g_rinv[f / 16];
    s.x *= rv; s.y *= rv; s.z *= rv; s.w *= rv;
    *(float4*)(ctx + i) = s;
}

// ---------------------------------------------------------------------------
extern "C" void kernel_launch(void* const* d_in, const int* in_sizes, int n_in,
                              void* d_out, int out_size)
{
    const float*        Q    = (const float*)d_in[0];
    const float*        K    = (const float*)d_in[1];
    const float*        V    = (const float*)d_in[2];
    const unsigned int* mask = (const unsigned int*)d_in[4];  // attn_mask_if
    const float*        iat  = (const float*)d_in[5];
    const float*        iaf  = (const float*)d_in[6];

    float* ctx  = (float*)d_out;
    float* attn = ctx + (size_t)NBH * SQ * DH;

    const int smem1 = 2 * 128 * 68 * 4;                       // 69632
    const int smem2 = 512 + (2 * 128 * TS + 2 * 64 * TS) * 2; // 55808
    cudaFuncSetAttribute(k_scores, cudaFuncAttributeMaxDynamicSharedMemorySize, smem1);
    cudaFuncSetAttribute(k_pv,     cudaFuncAttributeMaxDynamicSharedMemorySize, smem2);

    k_vsplit<<<(NBH * SQ * DH) / 1024, 256>>>(V);

    dim3 g1(8, 8, NBH);
    k_scores<<<g1, 256, smem1>>>(Q, K, iat, iaf, mask, attn);

    k_rowsum<<<(NBH * SQ) / 256, 256>>>();

    dim3 g2(8, NBH, KSPLIT);
    k_pv<<<g2, 256, smem2>>>(attn);

    k_ctx<<<(NBH * SQ * DH) / 1024, 256>>>(ctx);
}